// round 6
// baseline (speedup 1.0000x reference)
#include <cuda_runtime.h>
#include <cuda_fp16.h>
#include <math_constants.h>
#include <cstdint>

// ---------------- scratch (__device__ globals; no allocations) -------------
// A: signs, [40960 rows][96 cols] fp16 (2 repeats of 45 signs, each pad to 48)
// BT: H1 2-term fp16 split, [4096 rows(n)][96 cols(k)], col t*48+k
__device__ __align__(16) __half g_A[40960 * 96];
__device__ __align__(16) __half g_BT[4096 * 96];
__device__ float g_pval[8][40960];
__device__ int   g_pidx[8][40960];

__device__ __forceinline__ uint32_t smem_u32(const void* p) {
    uint32_t a;
    asm("{ .reg .u64 t; cvta.to.shared.u64 t, %1; cvt.u32.u64 %0, t; }" : "=r"(a) : "l"(p));
    return a;
}
__device__ __forceinline__ void ldmatrix_x4(uint32_t* r, uint32_t addr) {
    asm volatile("ldmatrix.sync.aligned.m8n8.x4.shared.b16 {%0,%1,%2,%3}, [%4];"
                 : "=r"(r[0]), "=r"(r[1]), "=r"(r[2]), "=r"(r[3]) : "r"(addr));
}
__device__ __forceinline__ void mma_f16(float* c, const uint32_t* a, const uint32_t* b) {
    asm volatile(
        "mma.sync.aligned.m16n8k16.row.col.f32.f16.f16.f32 "
        "{%0,%1,%2,%3}, {%4,%5,%6,%7}, {%8,%9}, {%0,%1,%2,%3};"
        : "+f"(c[0]), "+f"(c[1]), "+f"(c[2]), "+f"(c[3])
        : "r"(a[0]), "r"(a[1]), "r"(a[2]), "r"(a[3]), "r"(b[0]), "r"(b[1]));
}
__device__ __forceinline__ void cp16(uint32_t dst, const void* src) {
    asm volatile("cp.async.cg.shared.global [%0], [%1], 16;" :: "r"(dst), "l"(src));
}
#define CP_COMMIT() asm volatile("cp.async.commit_group;" ::: "memory")
#define CP_WAIT(n)  asm volatile("cp.async.wait_group %0;" :: "n"(n) : "memory")

// ---------------------------------------------------------------------------
// Prep 1: signs -> g_A. Row (bp*10+g), col t*48+k = sign at j=g*45+k (k<45).
// ---------------------------------------------------------------------------
__global__ void prep_signs(const float* __restrict__ x,
                           const float* __restrict__ S1,
                           const float* __restrict__ T1)
{
    __shared__ float s_sm[456];
    const int bp  = blockIdx.x;
    const int tid = threadIdx.x;
    const float* xr = x + (bp >> 3) * 480 + (bp & 7) * 60;
    for (int f = tid; f < 450; f += 128) {
        const int c = f / 15, kk = f - c * 15;
        float v = xr[2 * c] * S1[(2 * c) * 15 + kk];
        v = fmaf(xr[2 * c + 1], S1[(2 * c + 1) * 15 + kk], v);
        v = v - T1[c * 15 + kk];
        v = v - 1e-4f;
        s_sm[f] = (v > 0.0f) ? 1.0f : ((v < 0.0f) ? -1.0f : 0.0f);
    }
    __syncthreads();
    for (int f = tid; f < 960; f += 128) {
        const int g = f / 96, col = f - g * 96;
        const int k = col % 48;
        const float s = (k < 45) ? s_sm[g * 45 + k] : 0.0f;
        g_A[(size_t)(bp * 10 + g) * 96 + col] = __float2half_rn(s);
    }
}

// ---------------------------------------------------------------------------
// Prep 2: 2-term exact fp16 split of H1^T into g_BT[n][t*48+k].
// ---------------------------------------------------------------------------
__global__ void prep_split(const float* __restrict__ H1)
{
    const int i = blockIdx.x * 256 + threadIdx.x;   // over 4096*96
    if (i >= 4096 * 96) return;
    const int n = i / 96, col = i - n * 96;
    const int t = col / 48, k = col - t * 48;
    __half out = __float2half_rn(0.0f);
    if (k < 45) {
        const float h = H1[k * 4096 + n];
        const __half a = __float2half_rn(h);
        if (t == 0) out = a;
        else        out = __float2half_rn(h - __half2float(a));
    }
    g_BT[i] = out;
}

// ---------------------------------------------------------------------------
// Main HMMA kernel. Grid 2560 = 320 M-blocks x 8 N-eighths, 256 threads.
// CTA tile 128M x 128N, K=96 (6 k-steps), 4 N-iters. A resident; B double-
// buffered via cp.async. Smem rows padded to 208 B (20-bank row stride mod 32
// => conflict-free ldmatrix).
// ---------------------------------------------------------------------------
static constexpr int ROWB    = 208;
static constexpr int TILE_B  = 128 * ROWB;             // 26624
static constexpr int SM_A    = 0;
static constexpr int SM_B    = TILE_B;                 // buf0; buf1 at +TILE_B
static constexpr int SM_RED  = 3 * TILE_B;             // 79872
static constexpr int SMEM_BYTES = SM_RED + 4096;       // + sval/sidx = 83968

__global__ __launch_bounds__(256, 2)
void mma_kernel()
{
    extern __shared__ __align__(16) char smem[];
    const uint32_t sb = smem_u32(smem);
    float* sval = reinterpret_cast<float*>(smem + SM_RED);
    int*   sidx = reinterpret_cast<int*>(smem + SM_RED + 2048);

    const int tid = threadIdx.x;
    const int wid = tid >> 5;
    const int l   = tid & 31;
    const int q   = l & 3;
    const int wx  = wid >> 2;          // 0..1 (M half)
    const int wy  = wid & 3;           // 0..3 (N quarter of tile)
    const int mb  = blockIdx.x >> 3;   // 0..319
    const int nq  = blockIdx.x & 7;    // 0..7

    // ---- prologue: A tile + B tile 0 via cp.async (one commit group) ----
    {
        const size_t m0 = (size_t)mb * 128;
#pragma unroll
        for (int i = 0; i < 6; i++) {
            const int v = tid + i * 256;           // 1536 chunks
            const int row = v / 12, ch = v - row * 12;
            cp16(sb + SM_A + row * ROWB + ch * 16, g_A + (m0 + row) * 96 + ch * 8);
        }
        const size_t n0 = (size_t)nq * 512;
#pragma unroll
        for (int i = 0; i < 6; i++) {
            const int v = tid + i * 256;
            const int row = v / 12, ch = v - row * 12;
            cp16(sb + SM_B + row * ROWB + ch * 16, g_BT + (n0 + row) * 96 + ch * 8);
        }
        CP_COMMIT();
    }

    // ldmatrix base addresses (k advances +32B per k-step)
    uint32_t a_addr[4], b_addr[2];
#pragma unroll
    for (int mt = 0; mt < 4; mt++) {
        const int r = wx * 64 + mt * 16 + (l & 7) + 8 * ((l >> 3) & 1);
        a_addr[mt] = sb + SM_A + r * ROWB + (l >> 4) * 16;
    }
#pragma unroll
    for (int p2 = 0; p2 < 2; p2++) {
        // x4 B load: lane groups 0-7/8-15 -> nt=2*p2 (k0/k1 halves),
        //            lane groups 16-23/24-31 -> nt=2*p2+1.
        const int n = wy * 32 + p2 * 16 + ((l >> 4) & 1) * 8 + (l & 7);
        b_addr[p2] = sb + SM_B + n * ROWB + ((l >> 3) & 1) * 16;
    }

    float rv[8];
    int   ri[8];
#pragma unroll
    for (int s = 0; s < 8; s++) { rv[s] = -CUDART_INF_F; ri[s] = 0; }

#pragma unroll 1
    for (int it = 0; it < 4; it++) {
        const int n0 = nq * 512 + it * 128;

        // prefetch next B tile into the other buffer
        if (it < 3) {
            const size_t nn = (size_t)nq * 512 + (it + 1) * 128;
            const uint32_t bufo = ((it + 1) & 1) * TILE_B;
#pragma unroll
            for (int i = 0; i < 6; i++) {
                const int v = tid + i * 256;
                const int row = v / 12, ch = v - row * 12;
                cp16(sb + SM_B + bufo + row * ROWB + ch * 16,
                     g_BT + (nn + row) * 96 + ch * 8);
            }
            CP_COMMIT();
            CP_WAIT(1);
        } else {
            CP_WAIT(0);
        }
        __syncthreads();

        const uint32_t boff = (it & 1) * TILE_B;

        float acc[4][4][4];
#pragma unroll
        for (int mt = 0; mt < 4; mt++)
#pragma unroll
            for (int nt = 0; nt < 4; nt++) {
                acc[mt][nt][0] = 0.f; acc[mt][nt][1] = 0.f;
                acc[mt][nt][2] = 0.f; acc[mt][nt][3] = 0.f;
            }

#pragma unroll
        for (int ks = 0; ks < 6; ks++) {
            uint32_t af[4][4], bf[4][2];
#pragma unroll
            for (int mt = 0; mt < 4; mt++) ldmatrix_x4(af[mt], a_addr[mt] + ks * 32);
#pragma unroll
            for (int p2 = 0; p2 < 2; p2++) {
                uint32_t t4[4];
                ldmatrix_x4(t4, b_addr[p2] + boff + ks * 32);
                bf[2 * p2 + 0][0] = t4[0]; bf[2 * p2 + 0][1] = t4[1];
                bf[2 * p2 + 1][0] = t4[2]; bf[2 * p2 + 1][1] = t4[3];
            }
#pragma unroll
            for (int mt = 0; mt < 4; mt++)
#pragma unroll
                for (int nt = 0; nt < 4; nt++)
                    mma_f16(acc[mt][nt], af[mt], bf[nt]);
        }

        // running argmax from fragments (c0:(row l/4,col 2q), c1:+1col, c2/3:+8row)
#pragma unroll
        for (int mt = 0; mt < 4; mt++) {
#pragma unroll
            for (int nt = 0; nt < 4; nt++) {
                const int col0 = n0 + wy * 32 + nt * 8 + 2 * q;
                const int s0 = mt * 2, s1 = mt * 2 + 1;
                if (acc[mt][nt][0] > rv[s0]) { rv[s0] = acc[mt][nt][0]; ri[s0] = col0; }
                if (acc[mt][nt][1] > rv[s0]) { rv[s0] = acc[mt][nt][1]; ri[s0] = col0 + 1; }
                if (acc[mt][nt][2] > rv[s1]) { rv[s1] = acc[mt][nt][2]; ri[s1] = col0; }
                if (acc[mt][nt][3] > rv[s1]) { rv[s1] = acc[mt][nt][3]; ri[s1] = col0 + 1; }
            }
        }
        __syncthreads();   // compute done before next iter overwrites this buffer
    }

    // ---- reduce over the 4 lanes sharing each row, idx tiebreak ----
#pragma unroll
    for (int off = 1; off <= 2; off <<= 1) {
#pragma unroll
        for (int s = 0; s < 8; s++) {
            const float ov = __shfl_xor_sync(0xffffffffu, rv[s], off);
            const int   oi = __shfl_xor_sync(0xffffffffu, ri[s], off);
            if (ov > rv[s] || (ov == rv[s] && oi < ri[s])) { rv[s] = ov; ri[s] = oi; }
        }
    }
    if (q == 0) {
#pragma unroll
        for (int mt = 0; mt < 4; mt++) {
#pragma unroll
            for (int half = 0; half < 2; half++) {
                const int row = wx * 64 + mt * 16 + 8 * half + (l >> 2);
                sval[wy * 128 + row] = rv[mt * 2 + half];
                sidx[wy * 128 + row] = ri[mt * 2 + half];
            }
        }
    }
    __syncthreads();

    if (tid < 128) {
        float bv = sval[tid];
        int   bi = sidx[tid];
#pragma unroll
        for (int w = 1; w < 4; w++) {
            const float ov = sval[w * 128 + tid];
            const int   oi = sidx[w * 128 + tid];
            if (ov > bv || (ov == bv && oi < bi)) { bv = ov; bi = oi; }
        }
        g_pval[nq][mb * 128 + tid] = bv;
        g_pidx[nq][mb * 128 + tid] = bi;
    }
}

// ---------------------------------------------------------------------------
// Stage 2 (fused with argmax merge + LUT1 gather). Grid 512 blocks.
// ---------------------------------------------------------------------------
__global__ __launch_bounds__(128, 8)
void stage2_kernel(const float* __restrict__ LUT1,
                   const float* __restrict__ S2,
                   const float* __restrict__ H2,
                   const float* __restrict__ T2,
                   const float* __restrict__ LUT2,
                   float* __restrict__ out)
{
    __shared__ float z[16];
    __shared__ int   sidx2[8];
    __shared__ float logits[100];
    __shared__ float s_lse;

    const int b   = blockIdx.x;
    const int tid = threadIdx.x;

    // merge 8 N-eighths (ascending n => strict > keeps first occurrence),
    // gather LUT1, accumulate z deterministically (g ascending).
    if (tid < 8) {
        const int bp = b * 8 + tid;
        float z0 = 0.0f, z1 = 0.0f;
#pragma unroll
        for (int g = 0; g < 10; g++) {
            const int m = bp * 10 + g;
            float bv = g_pval[0][m];
            int   bi = g_pidx[0][m];
#pragma unroll
            for (int qq = 1; qq < 8; qq++) {
                const float v = g_pval[qq][m];
                if (v > bv) { bv = v; bi = g_pidx[qq][m]; }
            }
            z0 += LUT1[(g * 4096 + bi) * 2 + 0];
            z1 += LUT1[(g * 4096 + bi) * 2 + 1];
        }
        z[tid * 2 + 0] = z0;
        z[tid * 2 + 1] = z1;
    }
    __syncthreads();

    if (tid < 8) {
        const int c = tid;
        float w[15];
#pragma unroll
        for (int k = 0; k < 15; k++) {
            float v = z[2 * c + 0] * S2[(c * 2 + 0) * 15 + k];
            v = fmaf(z[2 * c + 1], S2[(c * 2 + 1) * 15 + k], v);
            v = v - T2[c * 15 + k];
            w[k] = (v > 0.0f) ? 1.0f : -1.0f;   // where(v==0,-1,sign(v))
        }
        float bm = -CUDART_INF_F;
        int   bi = 0;
#pragma unroll
        for (int m = 0; m < 16; m++) {
            float sc = 0.0f;
#pragma unroll
            for (int k = 0; k < 15; k++) sc = fmaf(w[k], H2[k * 16 + m], sc);
            if (sc > bm) { bm = sc; bi = m; }
        }
        sidx2[c] = bi;
    }
    __syncthreads();

    if (tid < 100) {
        float lsum = 0.0f;
#pragma unroll
        for (int c = 0; c < 8; c++) lsum += LUT2[(c * 16 + sidx2[c]) * 100 + tid];
        logits[tid] = lsum;
    }
    __syncthreads();

    if (tid == 0) {
        float mx = logits[0];
        for (int m = 1; m < 100; m++) mx = fmaxf(mx, logits[m]);
        float s = 0.0f;
        for (int m = 0; m < 100; m++) s += expf(logits[m] - mx);
        s_lse = mx + logf(s);
    }
    __syncthreads();

    if (tid < 100) out[b * 100 + tid] = logits[tid] - s_lse;
}

// ---------------------------------------------------------------------------
extern "C" void kernel_launch(void* const* d_in, const int* in_sizes, int n_in,
                              void* d_out, int out_size)
{
    const float* x    = (const float*)d_in[0];
    const float* S1   = (const float*)d_in[1];
    const float* H1   = (const float*)d_in[2];
    const float* T1   = (const float*)d_in[3];
    const float* LUT1 = (const float*)d_in[4];
    const float* S2   = (const float*)d_in[5];
    const float* H2   = (const float*)d_in[6];
    const float* T2   = (const float*)d_in[7];
    const float* LUT2 = (const float*)d_in[8];
    float* out = (float*)d_out;

    static bool attr_set = false;
    if (!attr_set) {
        cudaFuncSetAttribute(mma_kernel, cudaFuncAttributeMaxDynamicSharedMemorySize,
                             SMEM_BYTES);
        attr_set = true;
    }

    prep_signs<<<4096, 128>>>(x, S1, T1);
    prep_split<<<1536, 256>>>(H1);
    mma_kernel<<<2560, 256, SMEM_BYTES>>>();
    stage2_kernel<<<512, 128>>>(LUT1, S2, H2, T2, LUT2, out);
}

// round 7
// speedup vs baseline: 1.0037x; 1.0037x over previous
#include <cuda_runtime.h>
#include <cuda_fp16.h>
#include <math_constants.h>
#include <cstdint>

// ---------------- scratch (__device__ globals; no allocations) -------------
// A: signs, [40960 rows][96 cols] fp16 (2 repeats of 45 signs, each pad to 48)
// BT: H1 2-term fp16 split, [4096 rows(n)][96 cols(k)], col t*48+k
__device__ __align__(16) __half g_A[40960 * 96];
__device__ __align__(16) __half g_BT[4096 * 96];
__device__ float g_pval[8][40960];
__device__ int   g_pidx[8][40960];

__device__ __forceinline__ uint32_t smem_u32(const void* p) {
    uint32_t a;
    asm("{ .reg .u64 t; cvta.to.shared.u64 t, %1; cvt.u32.u64 %0, t; }" : "=r"(a) : "l"(p));
    return a;
}
__device__ __forceinline__ void ldmatrix_x4(uint32_t* r, uint32_t addr) {
    asm volatile("ldmatrix.sync.aligned.m8n8.x4.shared.b16 {%0,%1,%2,%3}, [%4];"
                 : "=r"(r[0]), "=r"(r[1]), "=r"(r[2]), "=r"(r[3]) : "r"(addr));
}
__device__ __forceinline__ void mma_f16(float* c, const uint32_t* a, const uint32_t* b) {
    asm volatile(
        "mma.sync.aligned.m16n8k16.row.col.f32.f16.f16.f32 "
        "{%0,%1,%2,%3}, {%4,%5,%6,%7}, {%8,%9}, {%0,%1,%2,%3};"
        : "+f"(c[0]), "+f"(c[1]), "+f"(c[2]), "+f"(c[3])
        : "r"(a[0]), "r"(a[1]), "r"(a[2]), "r"(a[3]), "r"(b[0]), "r"(b[1]));
}
__device__ __forceinline__ void cp16(uint32_t dst, const void* src) {
    asm volatile("cp.async.cg.shared.global [%0], [%1], 16;" :: "r"(dst), "l"(src));
}
#define CP_COMMIT() asm volatile("cp.async.commit_group;" ::: "memory")
#define CP_WAIT(n)  asm volatile("cp.async.wait_group %0;" :: "n"(n) : "memory")

static constexpr int NCTA   = 296;                 // 148 SM x 2 CTA
static constexpr int NJOBS  = 2560;                // 320 mb x 8 nq
static constexpr int ROWB   = 208;                 // smem row pitch (conflict-free)
static constexpr int TILE   = 128 * ROWB;          // 26624 per buffer
static constexpr int SM_A0  = 0;                   // A buf 0 / 1
static constexpr int SM_B0  = 2 * TILE;            // B buf 0 / 1
static constexpr int SM_RED = 4 * TILE;            // 106496
static constexpr int SMEM_BYTES = SM_RED + 4096;   // 110592

// ---------------------------------------------------------------------------
// Fused prep: blocks [0,4096) = signs -> g_A ; blocks [4096,5632) = H1 split.
// ---------------------------------------------------------------------------
__global__ void prep_kernel(const float* __restrict__ x,
                            const float* __restrict__ S1,
                            const float* __restrict__ T1,
                            const float* __restrict__ H1)
{
    const int tid = threadIdx.x;
    if (blockIdx.x < 4096) {
        __shared__ float s_sm[456];
        const int bp = blockIdx.x;
        const float* xr = x + (bp >> 3) * 480 + (bp & 7) * 60;
        for (int f = tid; f < 450; f += 256) {
            const int c = f / 15, kk = f - c * 15;
            float v = xr[2 * c] * S1[(2 * c) * 15 + kk];
            v = fmaf(xr[2 * c + 1], S1[(2 * c + 1) * 15 + kk], v);
            v = v - T1[c * 15 + kk];
            v = v - 1e-4f;
            s_sm[f] = (v > 0.0f) ? 1.0f : ((v < 0.0f) ? -1.0f : 0.0f);
        }
        __syncthreads();
        for (int f = tid; f < 960; f += 256) {
            const int g = f / 96, col = f - g * 96;
            const int k = col % 48;
            const float s = (k < 45) ? s_sm[g * 45 + k] : 0.0f;
            g_A[(size_t)(bp * 10 + g) * 96 + col] = __float2half_rn(s);
        }
    } else {
        const int i = (blockIdx.x - 4096) * 256 + tid;   // over 4096*96
        if (i >= 4096 * 96) return;
        const int n = i / 96, col = i - n * 96;
        const int t = col / 48, k = col - t * 48;
        __half out = __float2half_rn(0.0f);
        if (k < 45) {
            const float h = H1[k * 4096 + n];
            const __half a = __float2half_rn(h);
            if (t == 0) out = a;
            else        out = __float2half_rn(h - __half2float(a));
        }
        g_BT[i] = out;
    }
}

// ---------------------------------------------------------------------------
// Persistent HMMA kernel. 296 CTAs; jobs = mb*8+nq, strided by 296.
// Per job: CTA tile 128M x 128N, K=96 (6 k-steps), 4 N-iters.
// A and B double-buffered; next job's A+B0 prefetched during the last iter.
// ---------------------------------------------------------------------------
__global__ __launch_bounds__(256, 2)
void mma_kernel()
{
    extern __shared__ __align__(16) char smem[];
    const uint32_t sb = smem_u32(smem);
    float* sval = reinterpret_cast<float*>(smem + SM_RED);
    int*   sidx = reinterpret_cast<int*>(smem + SM_RED + 2048);

    const int tid = threadIdx.x;
    const int wid = tid >> 5;
    const int l   = tid & 31;
    const int q   = l & 3;
    const int wx  = wid >> 2;          // 0..1 (M half)
    const int wy  = wid & 3;           // 0..3 (N quarter of tile)
    const int cta = blockIdx.x;

    if (cta >= NJOBS) return;

    // chunk mapping for cp.async loops (1536 16B chunks per tile)
    int crow[6], cch[6];
#pragma unroll
    for (int i = 0; i < 6; i++) {
        const int v = tid + i * 256;
        crow[i] = v / 12;
        cch[i]  = v - crow[i] * 12;
    }

    // ---- prologue: first job's A + B0 (one group) ----
    {
        const int job = cta;
        const size_t m0 = (size_t)(job >> 3) * 128;
        const size_t n0 = (size_t)(job & 7) * 512;
#pragma unroll
        for (int i = 0; i < 6; i++)
            cp16(sb + SM_A0 + crow[i] * ROWB + cch[i] * 16,
                 g_A + (m0 + crow[i]) * 96 + cch[i] * 8);
#pragma unroll
        for (int i = 0; i < 6; i++)
            cp16(sb + SM_B0 + crow[i] * ROWB + cch[i] * 16,
                 g_BT + (n0 + crow[i]) * 96 + cch[i] * 8);
        CP_COMMIT();
    }

    // buffer-relative ldmatrix lane offsets
    uint32_t a_off[4], b_off[2];
#pragma unroll
    for (int mt = 0; mt < 4; mt++) {
        const int r = wx * 64 + mt * 16 + (l & 7) + 8 * ((l >> 3) & 1);
        a_off[mt] = r * ROWB + (l >> 4) * 16;
    }
#pragma unroll
    for (int p2 = 0; p2 < 2; p2++) {
        const int n = wy * 32 + p2 * 16 + ((l >> 4) & 1) * 8 + (l & 7);
        b_off[p2] = n * ROWB + ((l >> 3) & 1) * 16;
    }

    int abuf = 0, bbuf = 0;

#pragma unroll 1
    for (int job = cta; job < NJOBS; job += NCTA) {
        const int mb = job >> 3;
        const int nq = job & 7;

        float rv[8];
        int   ri[8];
#pragma unroll
        for (int s = 0; s < 8; s++) { rv[s] = -CUDART_INF_F; ri[s] = 0; }

#pragma unroll 1
        for (int it = 0; it < 4; it++) {
            const int n0 = nq * 512 + it * 128;

            if (it < 3) {
                // prefetch next B tile of this job
                const size_t nn = (size_t)nq * 512 + (it + 1) * 128;
                const uint32_t bo = SM_B0 + (bbuf ^ 1) * TILE;
#pragma unroll
                for (int i = 0; i < 6; i++)
                    cp16(sb + bo + crow[i] * ROWB + cch[i] * 16,
                         g_BT + (nn + crow[i]) * 96 + cch[i] * 8);
                CP_COMMIT();
                CP_WAIT(1);
            } else if (job + NCTA < NJOBS) {
                // prefetch next job's A + B0
                const int nj = job + NCTA;
                const size_t m0 = (size_t)(nj >> 3) * 128;
                const size_t nn = (size_t)(nj & 7) * 512;
                const uint32_t ao = SM_A0 + (abuf ^ 1) * TILE;
                const uint32_t bo = SM_B0 + (bbuf ^ 1) * TILE;
#pragma unroll
                for (int i = 0; i < 6; i++)
                    cp16(sb + ao + crow[i] * ROWB + cch[i] * 16,
                         g_A + (m0 + crow[i]) * 96 + cch[i] * 8);
#pragma unroll
                for (int i = 0; i < 6; i++)
                    cp16(sb + bo + crow[i] * ROWB + cch[i] * 16,
                         g_BT + (nn + crow[i]) * 96 + cch[i] * 8);
                CP_COMMIT();
                CP_WAIT(1);
            } else {
                CP_WAIT(0);
            }
            __syncthreads();

            const uint32_t abase = sb + SM_A0 + abuf * TILE;
            const uint32_t bbase = sb + SM_B0 + bbuf * TILE;

            float acc[4][4][4];
#pragma unroll
            for (int mt = 0; mt < 4; mt++)
#pragma unroll
                for (int nt = 0; nt < 4; nt++) {
                    acc[mt][nt][0] = 0.f; acc[mt][nt][1] = 0.f;
                    acc[mt][nt][2] = 0.f; acc[mt][nt][3] = 0.f;
                }

#pragma unroll
            for (int ks = 0; ks < 6; ks++) {
                uint32_t af[4][4], bf[4][2];
#pragma unroll
                for (int mt = 0; mt < 4; mt++)
                    ldmatrix_x4(af[mt], abase + a_off[mt] + ks * 32);
#pragma unroll
                for (int p2 = 0; p2 < 2; p2++) {
                    uint32_t t4[4];
                    ldmatrix_x4(t4, bbase + b_off[p2] + ks * 32);
                    bf[2 * p2 + 0][0] = t4[0]; bf[2 * p2 + 0][1] = t4[1];
                    bf[2 * p2 + 1][0] = t4[2]; bf[2 * p2 + 1][1] = t4[3];
                }
#pragma unroll
                for (int mt = 0; mt < 4; mt++)
#pragma unroll
                    for (int nt = 0; nt < 4; nt++)
                        mma_f16(acc[mt][nt], af[mt], bf[nt]);
            }

            // running argmax (c0:(row l/4,col 2q), c1:+1col, c2/3:+8row)
#pragma unroll
            for (int mt = 0; mt < 4; mt++) {
#pragma unroll
                for (int nt = 0; nt < 4; nt++) {
                    const int col0 = n0 + wy * 32 + nt * 8 + 2 * q;
                    const int s0 = mt * 2, s1 = mt * 2 + 1;
                    if (acc[mt][nt][0] > rv[s0]) { rv[s0] = acc[mt][nt][0]; ri[s0] = col0; }
                    if (acc[mt][nt][1] > rv[s0]) { rv[s0] = acc[mt][nt][1]; ri[s0] = col0 + 1; }
                    if (acc[mt][nt][2] > rv[s1]) { rv[s1] = acc[mt][nt][2]; ri[s1] = col0; }
                    if (acc[mt][nt][3] > rv[s1]) { rv[s1] = acc[mt][nt][3]; ri[s1] = col0 + 1; }
                }
            }
            __syncthreads();   // compute done before buffers are overwritten
            bbuf ^= 1;
        }

        // ---- job epilogue: reduce over lanes sharing a row, then warps ----
#pragma unroll
        for (int off = 1; off <= 2; off <<= 1) {
#pragma unroll
            for (int s = 0; s < 8; s++) {
                const float ov = __shfl_xor_sync(0xffffffffu, rv[s], off);
                const int   oi = __shfl_xor_sync(0xffffffffu, ri[s], off);
                if (ov > rv[s] || (ov == rv[s] && oi < ri[s])) { rv[s] = ov; ri[s] = oi; }
            }
        }
        if (q == 0) {
#pragma unroll
            for (int mt = 0; mt < 4; mt++) {
#pragma unroll
                for (int half = 0; half < 2; half++) {
                    const int row = wx * 64 + mt * 16 + 8 * half + (l >> 2);
                    sval[wy * 128 + row] = rv[mt * 2 + half];
                    sidx[wy * 128 + row] = ri[mt * 2 + half];
                }
            }
        }
        __syncthreads();

        if (tid < 128) {
            float bv = sval[tid];
            int   bi = sidx[tid];
#pragma unroll
            for (int w = 1; w < 4; w++) {
                const float ov = sval[w * 128 + tid];
                const int   oi = sidx[w * 128 + tid];
                if (ov > bv || (ov == bv && oi < bi)) { bv = ov; bi = oi; }
            }
            g_pval[nq][mb * 128 + tid] = bv;
            g_pidx[nq][mb * 128 + tid] = bi;
        }
        __syncthreads();   // sval/sidx free for next job
        abuf ^= 1;
    }
}

// ---------------------------------------------------------------------------
// Stage 2 (fused merge + LUT1 gather, parallel merge). Grid 512 blocks.
// ---------------------------------------------------------------------------
__global__ __launch_bounds__(128, 8)
void stage2_kernel(const float* __restrict__ LUT1,
                   const float* __restrict__ S2,
                   const float* __restrict__ H2,
                   const float* __restrict__ T2,
                   const float* __restrict__ LUT2,
                   float* __restrict__ out)
{
    __shared__ float lutv[8][10][2];
    __shared__ float z[16];
    __shared__ int   sidx2[8];
    __shared__ float logits[100];
    __shared__ float s_lse;

    const int b   = blockIdx.x;
    const int tid = threadIdx.x;

    // parallel merge: 80 threads, one (p,g) each. Quarters ascending in n,
    // strict > keeps first occurrence.
    if (tid < 80) {
        const int p = tid / 10, g = tid - p * 10;
        const int m = (b * 8 + p) * 10 + g;
        float bv = g_pval[0][m];
        int   bi = g_pidx[0][m];
#pragma unroll
        for (int qq = 1; qq < 8; qq++) {
            const float v = g_pval[qq][m];
            if (v > bv) { bv = v; bi = g_pidx[qq][m]; }
        }
        lutv[p][g][0] = LUT1[(g * 4096 + bi) * 2 + 0];
        lutv[p][g][1] = LUT1[(g * 4096 + bi) * 2 + 1];
    }
    __syncthreads();

    // z accumulation, deterministic ascending-g order (matches reference sum)
    if (tid < 16) {
        const int p = tid >> 1, d = tid & 1;
        float acc = 0.0f;
#pragma unroll
        for (int g = 0; g < 10; g++) acc += lutv[p][g][d];
        z[p * 2 + d] = acc;
    }
    __syncthreads();

    if (tid < 8) {
        const int c = tid;
        float w[15];
#pragma unroll
        for (int k = 0; k < 15; k++) {
            float v = z[2 * c + 0] * S2[(c * 2 + 0) * 15 + k];
            v = fmaf(z[2 * c + 1], S2[(c * 2 + 1) * 15 + k], v);
            v = v - T2[c * 15 + k];
            w[k] = (v > 0.0f) ? 1.0f : -1.0f;   // where(v==0,-1,sign(v))
        }
        float bm = -CUDART_INF_F;
        int   bi = 0;
#pragma unroll
        for (int m = 0; m < 16; m++) {
            float sc = 0.0f;
#pragma unroll
            for (int k = 0; k < 15; k++) sc = fmaf(w[k], H2[k * 16 + m], sc);
            if (sc > bm) { bm = sc; bi = m; }
        }
        sidx2[c] = bi;
    }
    __syncthreads();

    if (tid < 100) {
        float lsum = 0.0f;
#pragma unroll
        for (int c = 0; c < 8; c++) lsum += LUT2[(c * 16 + sidx2[c]) * 100 + tid];
        logits[tid] = lsum;
    }
    __syncthreads();

    if (tid == 0) {
        float mx = logits[0];
        for (int m = 1; m < 100; m++) mx = fmaxf(mx, logits[m]);
        float s = 0.0f;
        for (int m = 0; m < 100; m++) s += expf(logits[m] - mx);
        s_lse = mx + logf(s);
    }
    __syncthreads();

    if (tid < 100) out[b * 100 + tid] = logits[tid] - s_lse;
}

// ---------------------------------------------------------------------------
extern "C" void kernel_launch(void* const* d_in, const int* in_sizes, int n_in,
                              void* d_out, int out_size)
{
    const float* x    = (const float*)d_in[0];
    const float* S1   = (const float*)d_in[1];
    const float* H1   = (const float*)d_in[2];
    const float* T1   = (const float*)d_in[3];
    const float* LUT1 = (const float*)d_in[4];
    const float* S2   = (const float*)d_in[5];
    const float* H2   = (const float*)d_in[6];
    const float* T2   = (const float*)d_in[7];
    const float* LUT2 = (const float*)d_in[8];
    float* out = (float*)d_out;

    static bool attr_set = false;
    if (!attr_set) {
        cudaFuncSetAttribute(mma_kernel, cudaFuncAttributeMaxDynamicSharedMemorySize,
                             SMEM_BYTES);
        attr_set = true;
    }

    prep_kernel<<<5632, 256>>>(x, S1, T1, H1);
    mma_kernel<<<NCTA, 256, SMEM_BYTES>>>();
    stage2_kernel<<<512, 128>>>(LUT1, S2, H2, T2, LUT2, out);
}

// round 8
// speedup vs baseline: 1.1129x; 1.1088x over previous
#include <cuda_runtime.h>
#include <cuda_fp16.h>
#include <math_constants.h>
#include <cstdint>

// ---------------- scratch (__device__ globals; no allocations) -------------
// A: signs, [40960 rows][96 cols] fp16 (2 repeats of 45 signs, each pad to 48)
// BT: H1 2-term fp16 split, [4096 rows(n)][96 cols(k)], col t*48+k
__device__ __align__(16) __half g_A[40960 * 96];
__device__ __align__(16) __half g_BT[4096 * 96];
__device__ float g_pval[4][40960];
__device__ int   g_pidx[4][40960];

__device__ __forceinline__ uint32_t smem_u32(const void* p) {
    uint32_t a;
    asm("{ .reg .u64 t; cvta.to.shared.u64 t, %1; cvt.u32.u64 %0, t; }" : "=r"(a) : "l"(p));
    return a;
}
__device__ __forceinline__ void ldmatrix_x4(uint32_t* r, uint32_t addr) {
    asm volatile("ldmatrix.sync.aligned.m8n8.x4.shared.b16 {%0,%1,%2,%3}, [%4];"
                 : "=r"(r[0]), "=r"(r[1]), "=r"(r[2]), "=r"(r[3]) : "r"(addr));
}
__device__ __forceinline__ void mma_f16(float* c, const uint32_t* a, const uint32_t* b) {
    asm volatile(
        "mma.sync.aligned.m16n8k16.row.col.f32.f16.f16.f32 "
        "{%0,%1,%2,%3}, {%4,%5,%6,%7}, {%8,%9}, {%0,%1,%2,%3};"
        : "+f"(c[0]), "+f"(c[1]), "+f"(c[2]), "+f"(c[3])
        : "r"(a[0]), "r"(a[1]), "r"(a[2]), "r"(a[3]), "r"(b[0]), "r"(b[1]));
}
__device__ __forceinline__ void cp16(uint32_t dst, const void* src) {
    asm volatile("cp.async.cg.shared.global [%0], [%1], 16;" :: "r"(dst), "l"(src));
}
#define CP_COMMIT() asm volatile("cp.async.commit_group;" ::: "memory")
#define CP_WAIT(n)  asm volatile("cp.async.wait_group %0;" :: "n"(n) : "memory")

// ---------------------------------------------------------------------------
// Fused prep. Blocks [0,512): signs for batch b (8 p's) -> g_A, vectorized.
// Blocks [512,576): H1 2-term fp16 split for 64 n-rows -> g_BT, coalesced.
// ---------------------------------------------------------------------------
__global__ __launch_bounds__(256)
void prep_kernel(const float* __restrict__ x,
                 const float* __restrict__ S1,
                 const float* __restrict__ T1,
                 const float* __restrict__ H1)
{
    const int tid = threadIdx.x;
    if (blockIdx.x < 512) {
        __shared__ float xs[480];
        __shared__ float ss[3600];           // 8p x 450 signs
        const int b = blockIdx.x;
        for (int i = tid; i < 480; i += 256) xs[i] = x[b * 480 + i];
        __syncthreads();
        for (int f = tid; f < 3600; f += 256) {
            const int p = f / 450, e = f - p * 450;
            const int c = e / 15, kk = e - c * 15;
            float v = xs[p * 60 + 2 * c] * S1[(2 * c) * 15 + kk];
            v = fmaf(xs[p * 60 + 2 * c + 1], S1[(2 * c + 1) * 15 + kk], v);
            v = v - T1[c * 15 + kk];
            v = v - 1e-4f;
            ss[f] = (v > 0.0f) ? 1.0f : ((v < 0.0f) ? -1.0f : 0.0f);
        }
        __syncthreads();
        // 80 rows x 12 uint4 chunks (8 halves each)
        for (int v = tid; v < 960; v += 256) {
            const int row = v / 12, ch = v - row * 12;   // row = p*10+g
            const int p = row / 10, g = row - p * 10;
            uint4 w;
            __half2* hp = reinterpret_cast<__half2*>(&w);
#pragma unroll
            for (int e2 = 0; e2 < 4; e2++) {
                const int c0 = ch * 8 + e2 * 2, c1 = c0 + 1;
                const int k0 = (c0 < 48) ? c0 : c0 - 48;
                const int k1 = (c1 < 48) ? c1 : c1 - 48;
                const float s0 = (k0 < 45) ? ss[p * 450 + g * 45 + k0] : 0.0f;
                const float s1 = (k1 < 45) ? ss[p * 450 + g * 45 + k1] : 0.0f;
                hp[e2] = __halves2half2(__float2half_rn(s0), __float2half_rn(s1));
            }
            *reinterpret_cast<uint4*>(g_A + (size_t)(b * 80 + row) * 96 + ch * 8) = w;
        }
    } else {
        __shared__ __half bs[64][104];       // padded row (208B) for fewer conflicts
        const int n0 = (blockIdx.x - 512) * 64;
        const int nl = tid & 63;
        const int kg = tid >> 6;             // 0..3
#pragma unroll
        for (int kb = 0; kb < 48; kb += 4) {
            const int k = kb + kg;
            float h = 0.0f;
            if (k < 45) h = H1[(size_t)k * 4096 + n0 + nl];
            const __half a = __float2half_rn(h);
            bs[nl][k]      = a;
            bs[nl][48 + k] = __float2half_rn(h - __half2float(a));
        }
        __syncthreads();
        for (int v = tid; v < 768; v += 256) {
            const int row = v / 12, ch = v - row * 12;
            const uint4 w = *reinterpret_cast<const uint4*>(&bs[row][ch * 8]);
            *reinterpret_cast<uint4*>(g_BT + (size_t)(n0 + row) * 96 + ch * 8) = w;
        }
    }
}

// ---------------------------------------------------------------------------
// Main HMMA kernel (R5 shape). Grid 1280 = 320 M-blocks x 4 N-quarters,
// 256 threads. CTA tile 128M x 128N, K=96 (6 k-steps), 8 N-iters.
// A resident; B double-buffered via cp.async. ROWB=208 => conflict-free.
// ---------------------------------------------------------------------------
static constexpr int ROWB    = 208;
static constexpr int TILE_B  = 128 * ROWB;             // 26624
static constexpr int SM_A    = 0;
static constexpr int SM_B    = TILE_B;                 // buf0; buf1 at +TILE_B
static constexpr int SM_RED  = 3 * TILE_B;             // 79872
static constexpr int SMEM_BYTES = SM_RED + 4096;       // 83968

__global__ __launch_bounds__(256, 2)
void mma_kernel()
{
    extern __shared__ __align__(16) char smem[];
    const uint32_t sb = smem_u32(smem);
    float* sval = reinterpret_cast<float*>(smem + SM_RED);
    int*   sidx = reinterpret_cast<int*>(smem + SM_RED + 2048);

    const int tid = threadIdx.x;
    const int wid = tid >> 5;
    const int l   = tid & 31;
    const int q   = l & 3;
    const int wx  = wid >> 2;          // 0..1 (M half)
    const int wy  = wid & 3;           // 0..3 (N quarter of tile)
    const int mb  = blockIdx.x >> 2;   // 0..319
    const int nq  = blockIdx.x & 3;    // 0..3

    // ---- prologue: A tile + B tile 0 via cp.async (one commit group) ----
    {
        const size_t m0 = (size_t)mb * 128;
#pragma unroll
        for (int i = 0; i < 6; i++) {
            const int v = tid + i * 256;           // 1536 chunks
            const int row = v / 12, ch = v - row * 12;
            cp16(sb + SM_A + row * ROWB + ch * 16, g_A + (m0 + row) * 96 + ch * 8);
        }
        const size_t n0 = (size_t)nq * 1024;
#pragma unroll
        for (int i = 0; i < 6; i++) {
            const int v = tid + i * 256;
            const int row = v / 12, ch = v - row * 12;
            cp16(sb + SM_B + row * ROWB + ch * 16, g_BT + (n0 + row) * 96 + ch * 8);
        }
        CP_COMMIT();
    }

    // ldmatrix base addresses (k advances +32B per k-step)
    uint32_t a_addr[4], b_addr[2];
#pragma unroll
    for (int mt = 0; mt < 4; mt++) {
        const int r = wx * 64 + mt * 16 + (l & 7) + 8 * ((l >> 3) & 1);
        a_addr[mt] = sb + SM_A + r * ROWB + (l >> 4) * 16;
    }
#pragma unroll
    for (int p2 = 0; p2 < 2; p2++) {
        // x4 B load: lane groups 0-7/8-15 -> nt=2*p2 (k halves), 16-31 -> nt=2*p2+1
        const int n = wy * 32 + p2 * 16 + ((l >> 4) & 1) * 8 + (l & 7);
        b_addr[p2] = sb + SM_B + n * ROWB + ((l >> 3) & 1) * 16;
    }

    float rv[8];
    int   ri[8];
#pragma unroll
    for (int s = 0; s < 8; s++) { rv[s] = -CUDART_INF_F; ri[s] = 0; }

#pragma unroll 1
    for (int it = 0; it < 8; it++) {
        const int n0 = nq * 1024 + it * 128;

        if (it < 7) {
            const size_t nn = (size_t)nq * 1024 + (it + 1) * 128;
            const uint32_t bufo = ((it + 1) & 1) * TILE_B;
#pragma unroll
            for (int i = 0; i < 6; i++) {
                const int v = tid + i * 256;
                const int row = v / 12, ch = v - row * 12;
                cp16(sb + SM_B + bufo + row * ROWB + ch * 16,
                     g_BT + (nn + row) * 96 + ch * 8);
            }
            CP_COMMIT();
            CP_WAIT(1);
        } else {
            CP_WAIT(0);
        }
        __syncthreads();

        const uint32_t boff = (it & 1) * TILE_B;

        float acc[4][4][4];
#pragma unroll
        for (int mt = 0; mt < 4; mt++)
#pragma unroll
            for (int nt = 0; nt < 4; nt++) {
                acc[mt][nt][0] = 0.f; acc[mt][nt][1] = 0.f;
                acc[mt][nt][2] = 0.f; acc[mt][nt][3] = 0.f;
            }

#pragma unroll
        for (int ks = 0; ks < 6; ks++) {
            uint32_t af[4][4], bf[4][2];
#pragma unroll
            for (int mt = 0; mt < 4; mt++) ldmatrix_x4(af[mt], a_addr[mt] + ks * 32);
#pragma unroll
            for (int p2 = 0; p2 < 2; p2++) {
                uint32_t t4[4];
                ldmatrix_x4(t4, b_addr[p2] + boff + ks * 32);
                bf[2 * p2 + 0][0] = t4[0]; bf[2 * p2 + 0][1] = t4[1];
                bf[2 * p2 + 1][0] = t4[2]; bf[2 * p2 + 1][1] = t4[3];
            }
#pragma unroll
            for (int mt = 0; mt < 4; mt++)
#pragma unroll
                for (int nt = 0; nt < 4; nt++)
                    mma_f16(acc[mt][nt], af[mt], bf[nt]);
        }

        // running argmax (c0:(row l/4,col 2q), c1:+1col, c2/3:+8row)
#pragma unroll
        for (int mt = 0; mt < 4; mt++) {
#pragma unroll
            for (int nt = 0; nt < 4; nt++) {
                const int col0 = n0 + wy * 32 + nt * 8 + 2 * q;
                const int s0 = mt * 2, s1 = mt * 2 + 1;
                if (acc[mt][nt][0] > rv[s0]) { rv[s0] = acc[mt][nt][0]; ri[s0] = col0; }
                if (acc[mt][nt][1] > rv[s0]) { rv[s0] = acc[mt][nt][1]; ri[s0] = col0 + 1; }
                if (acc[mt][nt][2] > rv[s1]) { rv[s1] = acc[mt][nt][2]; ri[s1] = col0; }
                if (acc[mt][nt][3] > rv[s1]) { rv[s1] = acc[mt][nt][3]; ri[s1] = col0 + 1; }
            }
        }
        __syncthreads();   // compute done before next iter overwrites this buffer
    }

    // ---- reduce over the 4 lanes sharing each row, idx tiebreak ----
#pragma unroll
    for (int off = 1; off <= 2; off <<= 1) {
#pragma unroll
        for (int s = 0; s < 8; s++) {
            const float ov = __shfl_xor_sync(0xffffffffu, rv[s], off);
            const int   oi = __shfl_xor_sync(0xffffffffu, ri[s], off);
            if (ov > rv[s] || (ov == rv[s] && oi < ri[s])) { rv[s] = ov; ri[s] = oi; }
        }
    }
    if (q == 0) {
#pragma unroll
        for (int mt = 0; mt < 4; mt++) {
#pragma unroll
            for (int half = 0; half < 2; half++) {
                const int row = wx * 64 + mt * 16 + 8 * half + (l >> 2);
                sval[wy * 128 + row] = rv[mt * 2 + half];
                sidx[wy * 128 + row] = ri[mt * 2 + half];
            }
        }
    }
    __syncthreads();

    if (tid < 128) {
        float bv = sval[tid];
        int   bi = sidx[tid];
#pragma unroll
        for (int w = 1; w < 4; w++) {
            const float ov = sval[w * 128 + tid];
            const int   oi = sidx[w * 128 + tid];
            if (ov > bv || (ov == bv && oi < bi)) { bv = ov; bi = oi; }
        }
        g_pval[nq][mb * 128 + tid] = bv;
        g_pidx[nq][mb * 128 + tid] = bi;
    }
}

// ---------------------------------------------------------------------------
// Stage 2: fused parallel merge (4 quarters) + LUT1 gather + rest. Grid 512.
// ---------------------------------------------------------------------------
__global__ __launch_bounds__(128, 8)
void stage2_kernel(const float* __restrict__ LUT1,
                   const float* __restrict__ S2,
                   const float* __restrict__ H2,
                   const float* __restrict__ T2,
                   const float* __restrict__ LUT2,
                   float* __restrict__ out)
{
    __shared__ float lutv[8][10][2];
    __shared__ float z[16];
    __shared__ int   sidx2[8];
    __shared__ float logits[100];
    __shared__ float s_lse;

    const int b   = blockIdx.x;
    const int tid = threadIdx.x;

    // parallel merge: 80 threads, one (p,g) each. Quarters ascending in n,
    // strict > keeps first occurrence.
    if (tid < 80) {
        const int p = tid / 10, g = tid - p * 10;
        const int m = (b * 8 + p) * 10 + g;
        float bv = g_pval[0][m];
        int   bi = g_pidx[0][m];
#pragma unroll
        for (int qq = 1; qq < 4; qq++) {
            const float v = g_pval[qq][m];
            if (v > bv) { bv = v; bi = g_pidx[qq][m]; }
        }
        lutv[p][g][0] = LUT1[(g * 4096 + bi) * 2 + 0];
        lutv[p][g][1] = LUT1[(g * 4096 + bi) * 2 + 1];
    }
    __syncthreads();

    // z accumulation in deterministic ascending-g order (matches reference)
    if (tid < 16) {
        const int p = tid >> 1, d = tid & 1;
        float acc = 0.0f;
#pragma unroll
        for (int g = 0; g < 10; g++) acc += lutv[p][g][d];
        z[p * 2 + d] = acc;
    }
    __syncthreads();

    if (tid < 8) {
        const int c = tid;
        float w[15];
#pragma unroll
        for (int k = 0; k < 15; k++) {
            float v = z[2 * c + 0] * S2[(c * 2 + 0) * 15 + k];
            v = fmaf(z[2 * c + 1], S2[(c * 2 + 1) * 15 + k], v);
            v = v - T2[c * 15 + k];
            w[k] = (v > 0.0f) ? 1.0f : -1.0f;   // where(v==0,-1,sign(v))
        }
        float bm = -CUDART_INF_F;
        int   bi = 0;
#pragma unroll
        for (int m = 0; m < 16; m++) {
            float sc = 0.0f;
#pragma unroll
            for (int k = 0; k < 15; k++) sc = fmaf(w[k], H2[k * 16 + m], sc);
            if (sc > bm) { bm = sc; bi = m; }
        }
        sidx2[c] = bi;
    }
    __syncthreads();

    if (tid < 100) {
        float lsum = 0.0f;
#pragma unroll
        for (int c = 0; c < 8; c++) lsum += LUT2[(c * 16 + sidx2[c]) * 100 + tid];
        logits[tid] = lsum;
    }
    __syncthreads();

    if (tid == 0) {
        float mx = logits[0];
        for (int m = 1; m < 100; m++) mx = fmaxf(mx, logits[m]);
        float s = 0.0f;
        for (int m = 0; m < 100; m++) s += expf(logits[m] - mx);
        s_lse = mx + logf(s);
    }
    __syncthreads();

    if (tid < 100) out[b * 100 + tid] = logits[tid] - s_lse;
}

// ---------------------------------------------------------------------------
extern "C" void kernel_launch(void* const* d_in, const int* in_sizes, int n_in,
                              void* d_out, int out_size)
{
    const float* x    = (const float*)d_in[0];
    const float* S1   = (const float*)d_in[1];
    const float* H1   = (const float*)d_in[2];
    const float* T1   = (const float*)d_in[3];
    const float* LUT1 = (const float*)d_in[4];
    const float* S2   = (const float*)d_in[5];
    const float* H2   = (const float*)d_in[6];
    const float* T2   = (const float*)d_in[7];
    const float* LUT2 = (const float*)d_in[8];
    float* out = (float*)d_out;

    static bool attr_set = false;
    if (!attr_set) {
        cudaFuncSetAttribute(mma_kernel, cudaFuncAttributeMaxDynamicSharedMemorySize,
                             SMEM_BYTES);
        attr_set = true;
    }

    prep_kernel<<<576, 256>>>(x, S1, T1, H1);
    mma_kernel<<<1280, 256, SMEM_BYTES>>>();
    stage2_kernel<<<512, 128>>>(LUT1, S2, H2, T2, LUT2, out);
}